// round 1
// baseline (speedup 1.0000x reference)
#include <cuda_runtime.h>

// Problem constants (fixed for MoEDense_10411000726246)
#define TB 8192     // batch
#define DD 128      // input dim (K)
#define FF 128      // output dim (N)
#define TT 64       // num experts
#define TM 32       // rows per GEMM tile

#define MAX_TILES (TB / TM + TT)    // 320 (worst-case padded tiles)
#define PAD_CAP   (MAX_TILES * TM)  // 10240

// Scratch (no allocations allowed)
__device__ int g_counts[TT];
__device__ int g_cursor[TT];
__device__ int g_tileExpert[MAX_TILES];
__device__ int g_tileBase[MAX_TILES];
__device__ int g_rowOrder[PAD_CAP];

// ---------------------------------------------------------------------------
// K0: reset scratch (kernel must be deterministic across graph replays)
// ---------------------------------------------------------------------------
__global__ void k_init() {
    int i = blockIdx.x * blockDim.x + threadIdx.x;
    if (i < PAD_CAP)   g_rowOrder[i] = -1;
    if (i < MAX_TILES) { g_tileExpert[i] = -1; g_tileBase[i] = 0; }
    if (i < TT)        { g_counts[i] = 0; g_cursor[i] = 0; }
}

// ---------------------------------------------------------------------------
// K1: histogram of task_idx (smem bins, then one global atomic per bin/block)
// ---------------------------------------------------------------------------
__global__ void k_hist(const int* __restrict__ tidx) {
    __shared__ int s_bins[TT];
    int tid = threadIdx.x;
    if (tid < TT) s_bins[tid] = 0;
    __syncthreads();
    int b = blockIdx.x * blockDim.x + tid;
    if (b < TB) {
        int e = tidx[b];
        e = min(max(e, 0), TT - 1);
        atomicAdd(&s_bins[e], 1);
    }
    __syncthreads();
    if (tid < TT && s_bins[tid] > 0) atomicAdd(&g_counts[tid], s_bins[tid]);
}

// ---------------------------------------------------------------------------
// K2: plan — padded per-expert row offsets + tile table.
// Parallel loads (64 threads), tiny serial scan in smem (fast), parallel fill.
// ---------------------------------------------------------------------------
__global__ void k_plan() {
    __shared__ int s_nt[TT];
    __shared__ int s_toff[TT];
    __shared__ int s_roff[TT];
    int e = threadIdx.x;
    int nt = 0;
    if (e < TT) {
        int c = g_counts[e];
        nt = (c + TM - 1) / TM;
        s_nt[e] = nt;
    }
    __syncthreads();
    if (e == 0) {
        int toff = 0, roff = 0;
        #pragma unroll
        for (int i = 0; i < TT; i++) {
            s_toff[i] = toff;
            s_roff[i] = roff;
            toff += s_nt[i];
            roff += s_nt[i] * TM;
        }
    }
    __syncthreads();
    if (e < TT) {
        g_cursor[e] = s_roff[e];
        int tb = s_toff[e], rb = s_roff[e];
        for (int j = 0; j < nt; j++) {
            g_tileExpert[tb + j] = e;
            g_tileBase[tb + j]   = rb + j * TM;
        }
    }
}

// ---------------------------------------------------------------------------
// K3: counting-sort scatter (block-local bins -> one global atomic per bin)
// Order within an expert is nondeterministic but output values are identical.
// ---------------------------------------------------------------------------
__global__ void k_scatter(const int* __restrict__ tidx) {
    __shared__ int s_bins[TT];
    __shared__ int s_base[TT];
    int tid = threadIdx.x;
    if (tid < TT) s_bins[tid] = 0;
    __syncthreads();
    int b = blockIdx.x * blockDim.x + tid;
    int e = -1, loc = 0;
    if (b < TB) {
        e = tidx[b];
        e = min(max(e, 0), TT - 1);
        loc = atomicAdd(&s_bins[e], 1);
    }
    __syncthreads();
    if (tid < TT && s_bins[tid] > 0)
        s_base[tid] = atomicAdd(&g_cursor[tid], s_bins[tid]);
    __syncthreads();
    if (b < TB) g_rowOrder[s_base[e] + loc] = b;
}

// ---------------------------------------------------------------------------
// K4: grouped SGEMM. One block = one (expert, 32-row) tile, full N=128.
//   smem: As[128][32] transposed A (16KB) + Ws[128][128] weights (64KB)
//   128 threads, each computes 4 rows x 8 cols (32 fp32 accumulators).
// ---------------------------------------------------------------------------
#define SMEM_BYTES ((DD * TM + DD * FF) * 4 + TM * 4)

__global__ __launch_bounds__(128, 2)
void k_gemm(const float* __restrict__ X, const float* __restrict__ W,
            const float* __restrict__ Bias, float* __restrict__ Y) {
    extern __shared__ float smem[];
    float* As = smem;                 // [DD][TM]   transposed A
    float* Ws = smem + DD * TM;       // [DD][FF]   weights (k-major, like gmem)
    int* rows_s = (int*)(smem + DD * TM + DD * FF);

    int tile = blockIdx.x;
    int e = g_tileExpert[tile];
    if (e < 0) return;                // unused padding tile
    int base = g_tileBase[tile];
    int tid = threadIdx.x;

    if (tid < TM) rows_s[tid] = g_rowOrder[base + tid];
    __syncthreads();

    // Load A (32 rows x 128 k) transposed into As[k][i]; invalid rows -> 0.
    // idx: 1024 float4s; lanes sweep rows (conflict-free STS).
    #pragma unroll
    for (int it = 0; it < (TM * DD / 4) / 128; it++) {
        int idx = tid + it * 128;
        int i  = idx & (TM - 1);      // row in tile
        int k4 = idx >> 5;            // k/4
        int r = rows_s[i];
        float4 v = (r >= 0) ? *(const float4*)&X[r * DD + k4 * 4]
                            : make_float4(0.f, 0.f, 0.f, 0.f);
        As[(4 * k4 + 0) * TM + i] = v.x;
        As[(4 * k4 + 1) * TM + i] = v.y;
        As[(4 * k4 + 2) * TM + i] = v.z;
        As[(4 * k4 + 3) * TM + i] = v.w;
    }

    // Load W[e] (128x128 fp32 = 64KB), straight coalesced float4 copy.
    {
        const float4* Wg = (const float4*)(W + (size_t)e * DD * FF);
        float4* Wsv = (float4*)Ws;
        #pragma unroll
        for (int it = 0; it < (DD * FF / 4) / 128; it++)
            Wsv[tid + it * 128] = Wg[tid + it * 128];
    }
    __syncthreads();

    // Microkernel: thread (ri, ci) computes rows ri*4..+3, cols ci*8..+7
    int ri = tid >> 4;   // 0..7
    int ci = tid & 15;   // 0..15
    float acc[4][8];
    #pragma unroll
    for (int r = 0; r < 4; r++)
        #pragma unroll
        for (int c = 0; c < 8; c++) acc[r][c] = 0.f;

    #pragma unroll 8
    for (int k = 0; k < DD; k++) {
        float4 a  = *(const float4*)&As[k * TM + ri * 4];
        float4 b0 = *(const float4*)&Ws[k * FF + ci * 8];
        float4 b1 = *(const float4*)&Ws[k * FF + ci * 8 + 4];
        float av[4] = {a.x, a.y, a.z, a.w};
        float bv[8] = {b0.x, b0.y, b0.z, b0.w, b1.x, b1.y, b1.z, b1.w};
        #pragma unroll
        for (int r = 0; r < 4; r++)
            #pragma unroll
            for (int c = 0; c < 8; c++)
                acc[r][c] = fmaf(av[r], bv[c], acc[r][c]);
    }

    // Epilogue: add bias, store valid rows (vectorized).
    float4 bias0 = *(const float4*)&Bias[e * FF + ci * 8];
    float4 bias1 = *(const float4*)&Bias[e * FF + ci * 8 + 4];
    #pragma unroll
    for (int r = 0; r < 4; r++) {
        int row = rows_s[ri * 4 + r];
        if (row >= 0) {
            float4 o0 = make_float4(acc[r][0] + bias0.x, acc[r][1] + bias0.y,
                                    acc[r][2] + bias0.z, acc[r][3] + bias0.w);
            float4 o1 = make_float4(acc[r][4] + bias1.x, acc[r][5] + bias1.y,
                                    acc[r][6] + bias1.z, acc[r][7] + bias1.w);
            *(float4*)&Y[(size_t)row * FF + ci * 8]     = o0;
            *(float4*)&Y[(size_t)row * FF + ci * 8 + 4] = o1;
        }
    }
}

// ---------------------------------------------------------------------------
extern "C" void kernel_launch(void* const* d_in, const int* in_sizes, int n_in,
                              void* d_out, int out_size) {
    const float* X    = (const float*)d_in[0];   // [B, D] fp32
    const int*   tidx = (const int*)d_in[1];     // [B] int32
    const float* W    = (const float*)d_in[2];   // [T, D, F] fp32
    const float* Bias = (const float*)d_in[3];   // [T, F] fp32
    float* Y = (float*)d_out;                    // [B, F] fp32

    (void)in_sizes; (void)n_in; (void)out_size;

    cudaFuncSetAttribute(k_gemm, cudaFuncAttributeMaxDynamicSharedMemorySize,
                         SMEM_BYTES);

    k_init<<<(PAD_CAP + 255) / 256, 256>>>();
    k_hist<<<TB / 256, 256>>>(tidx);
    k_plan<<<1, TT>>>();
    k_scatter<<<TB / 256, 256>>>(tidx);
    k_gemm<<<MAX_TILES, 128, SMEM_BYTES>>>(X, W, Bias, Y);
}